// round 8
// baseline (speedup 1.0000x reference)
#include <cuda_runtime.h>
#include <math.h>

#define N_NODES 81
#define N_EDGES 1620
#define IN_DIM  10
#define HIDDEN  8192
#define ACTIONS 729

// ---------------- device scratch ----------------
__device__ float g_xc[N_NODES * IN_DIM];  // (A_norm @ x)
__device__ float g_gvec[HIDDEN];   // pooled raw LN sum (pre-affine)
__device__ float g_acc1[HIDDEN];   // GEMV1 accumulator
__device__ float g_acc2[ACTIONS];  // GEMV2 accumulator
__device__ unsigned int g_cnt;     // kE completion counter

__device__ __forceinline__ float warp_sum(float v) {
    #pragma unroll
    for (int o = 16; o > 0; o >>= 1) v += __shfl_xor_sync(0xffffffffu, v, o);
    return v;
}
__device__ __forceinline__ float warp_max(float v) {
    #pragma unroll
    for (int o = 16; o > 0; o >>= 1) v = fmaxf(v, __shfl_xor_sync(0xffffffffu, v, o));
    return v;
}

// ---------------- kZ: zero accumulators + edge aggregation (block 0) --------
#define ZTOT (HIDDEN + HIDDEN + ACTIONS + 1)
__global__ void __launch_bounds__(1024) kZ(const float* __restrict__ x,
                                           const int* __restrict__ eraw) {
    const int gi = blockIdx.x * 1024 + threadIdx.x;
    if (gi < HIDDEN) g_gvec[gi] = 0.f;
    else if (gi < 2 * HIDDEN) g_acc1[gi - HIDDEN] = 0.f;
    else if (gi < 2 * HIDDEN + ACTIONS) g_acc2[gi - 2 * HIDDEN] = 0.f;
    else if (gi == 2 * HIDDEN + ACTIONS) g_cnt = 0u;

    if (blockIdx.x != 0) return;
    // ---- block 0: GCN aggregation in input dim (A_norm @ x) ----
    __shared__ float degs[N_NODES];
    __shared__ float dinv[N_NODES];
    __shared__ float xcs[N_NODES * IN_DIM];
    __shared__ int is64s;
    const int t = threadIdx.x;

    if (t == 0) {
        int any_odd = 0;
        #pragma unroll 1
        for (int i = 0; i < 32; i++) {
            any_odd |= eraw[2 * i + 1];
            any_odd |= eraw[2 * (N_EDGES + i) + 1];
        }
        is64s = (any_odd == 0) ? 1 : 0;
    }
    if (t < N_NODES) degs[t] = 1.f;  // self loop
    for (int i = t; i < N_NODES * IN_DIM; i += 1024) xcs[i] = 0.f;
    __syncthreads();
    const int is64 = is64s;

    #define SRC(e) min(N_NODES - 1, max(0, is64 ? eraw[2 * (e)] : eraw[(e)]))
    #define DST(e) min(N_NODES - 1, max(0, is64 ? eraw[2 * (N_EDGES + (e))] : eraw[N_EDGES + (e)]))

    for (int e = t; e < N_EDGES; e += 1024)
        atomicAdd(&degs[DST(e)], 1.f);
    __syncthreads();
    if (t < N_NODES) dinv[t] = rsqrtf(degs[t]);
    __syncthreads();

    for (int e = t; e < N_EDGES; e += 1024) {
        int s = SRC(e), d = DST(e);
        float nm = dinv[s] * dinv[d];
        #pragma unroll
        for (int k = 0; k < IN_DIM; k++)
            atomicAdd(&xcs[d * IN_DIM + k], nm * x[s * IN_DIM + k]);
    }
    if (t < N_NODES) {
        float nm = dinv[t] * dinv[t];
        #pragma unroll
        for (int k = 0; k < IN_DIM; k++)
            atomicAdd(&xcs[t * IN_DIM + k], nm * x[t * IN_DIM + k]);
    }
    __syncthreads();
    for (int i = t; i < N_NODES * IN_DIM; i += 1024) g_xc[i] = xcs[i];
    #undef SRC
    #undef DST
}

// ---------------- kB: per-node dense row + relu + LN + pool (512 thr) ----
__global__ void __launch_bounds__(512) kB(const float* __restrict__ Wg,
                                          const float* __restrict__ bg) {
    const int n = blockIdx.x;
    const int t = threadIdx.x;
    __shared__ float xcs[IN_DIM];
    __shared__ float s1[16], s2[16], stat[2];

    if (t < IN_DIM) xcs[t] = g_xc[n * IN_DIM + t];
    __syncthreads();

    const float c0 = xcs[0], c1 = xcs[1], c2 = xcs[2], c3 = xcs[3], c4 = xcs[4];
    const float c5 = xcs[5], c6 = xcs[6], c7 = xcs[7], c8 = xcs[8], c9 = xcs[9];

    float h[HIDDEN / 512];   // 16 floats in registers
    float sum = 0.f, sumsq = 0.f;
    #pragma unroll
    for (int i = 0; i < HIDDEN / 512; i++) {
        const int j = t + i * 512;
        float v = bg[j];
        v = fmaf(c0, Wg[0 * HIDDEN + j], v);
        v = fmaf(c1, Wg[1 * HIDDEN + j], v);
        v = fmaf(c2, Wg[2 * HIDDEN + j], v);
        v = fmaf(c3, Wg[3 * HIDDEN + j], v);
        v = fmaf(c4, Wg[4 * HIDDEN + j], v);
        v = fmaf(c5, Wg[5 * HIDDEN + j], v);
        v = fmaf(c6, Wg[6 * HIDDEN + j], v);
        v = fmaf(c7, Wg[7 * HIDDEN + j], v);
        v = fmaf(c8, Wg[8 * HIDDEN + j], v);
        v = fmaf(c9, Wg[9 * HIDDEN + j], v);
        v = fmaxf(v, 0.f);
        h[i] = v;
        sum += v;
        sumsq = fmaf(v, v, sumsq);
    }
    sum = warp_sum(sum);
    sumsq = warp_sum(sumsq);
    const int w = t >> 5, l = t & 31;
    if (l == 0) { s1[w] = sum; s2[w] = sumsq; }
    __syncthreads();
    if (t == 0) {
        float a = 0.f, b = 0.f;
        #pragma unroll
        for (int i = 0; i < 16; i++) { a += s1[i]; b += s2[i]; }
        float mu = a * (1.f / HIDDEN);
        float var = b * (1.f / HIDDEN) - mu * mu;
        stat[0] = mu;
        stat[1] = rsqrtf(var + 1e-5f);
    }
    __syncthreads();
    const float mu = stat[0], rs = stat[1];
    #pragma unroll
    for (int i = 0; i < HIDDEN / 512; i++)
        atomicAdd(&g_gvec[t + i * 512], (h[i] - mu) * rs);
}

// ---------------- kD: split-K GEMV vs W1, LN affine fused into gs load ------
#define KC1 64
__global__ void __launch_bounds__(256) kD(const float* __restrict__ W1,
                                          const float* __restrict__ ln_g,
                                          const float* __restrict__ ln_b) {
    const int jc = blockIdx.x;    // 0..7   -> 1024-col chunk
    const int kc = blockIdx.y;    // 0..127 -> 64-row chunk
    const int t = threadIdx.x;
    __shared__ float gs[KC1];
    if (t < KC1) {
        const int k = kc * KC1 + t;
        gs[t] = fmaf(ln_g[k], g_gvec[k], (float)N_NODES * ln_b[k]);
    }
    __syncthreads();

    const int col = jc * 1024 + t * 4;
    const float4* Wp = reinterpret_cast<const float4*>(W1 + (size_t)(kc * KC1) * HIDDEN + col);
    float4 acc = make_float4(0.f, 0.f, 0.f, 0.f);
    #pragma unroll 8
    for (int k = 0; k < KC1; k++) {
        float4 wv = Wp[(size_t)k * (HIDDEN / 4)];
        float gv = gs[k];
        acc.x = fmaf(gv, wv.x, acc.x);
        acc.y = fmaf(gv, wv.y, acc.y);
        acc.z = fmaf(gv, wv.z, acc.z);
        acc.w = fmaf(gv, wv.w, acc.w);
    }
    atomicAdd(&g_acc1[col + 0], acc.x);
    atomicAdd(&g_acc1[col + 1], acc.y);
    atomicAdd(&g_acc1[col + 2], acc.z);
    atomicAdd(&g_acc1[col + 3], acc.w);
}

// ---------------- kE: split-K/split-N GEMV vs W2 + fused log_softmax -------
#define KC2 32
#define CCH 243                       // 729 / 3 columns per block
#define KE_BLOCKS ((HIDDEN / KC2) * 3)
__global__ void __launch_bounds__(256) kE(const float* __restrict__ W2,
                                          const float* __restrict__ b1,
                                          const float* __restrict__ b2,
                                          float* __restrict__ out) {
    const int kc = blockIdx.x;    // 0..255 -> 32-row chunk
    const int cc = blockIdx.y;    // 0..2   -> 243-col chunk
    const int t = threadIdx.x;
    __shared__ float ys[KC2];
    __shared__ float sm[8];
    __shared__ float bshared;
    __shared__ int lasts;

    if (t < KC2) {
        const int k = kc * KC2 + t;
        ys[t] = fmaxf(g_acc1[k] + b1[k], 0.f);
    }
    __syncthreads();

    const int c = cc * CCH + t;
    if (t < CCH) {
        const float* Wp = W2 + (size_t)(kc * KC2) * ACTIONS + c;
        // fully unrolled: all 32 loads in flight (MLP=32), then FMAs
        float wv[KC2];
        #pragma unroll
        for (int k = 0; k < KC2; k++)
            wv[k] = Wp[(size_t)k * ACTIONS];
        float a = 0.f;
        #pragma unroll
        for (int k = 0; k < KC2; k++)
            a = fmaf(ys[k], wv[k], a);
        atomicAdd(&g_acc2[c], a);
    }

    // completion counter: last block computes log_softmax
    __threadfence();
    __syncthreads();
    if (t == 0) lasts = (atomicAdd(&g_cnt, 1u) == KE_BLOCKS - 1) ? 1 : 0;
    __syncthreads();
    if (!lasts) return;
    __threadfence();

    float v0 = (t < ACTIONS)        ? (g_acc2[t]        + b2[t])        : -3.4e38f;
    float v1 = (t + 256 < ACTIONS)  ? (g_acc2[t + 256]  + b2[t + 256])  : -3.4e38f;
    float v2 = (t + 512 < ACTIONS)  ? (g_acc2[t + 512]  + b2[t + 512])  : -3.4e38f;

    float m = fmaxf(v0, fmaxf(v1, v2));
    m = warp_max(m);
    if ((t & 31) == 0) sm[t >> 5] = m;
    __syncthreads();
    if (t < 8) {
        float mm = sm[t];
        #pragma unroll
        for (int o = 4; o > 0; o >>= 1) mm = fmaxf(mm, __shfl_xor_sync(0xffu, mm, o));
        if (t == 0) bshared = mm;
    }
    __syncthreads();
    const float mx = bshared;

    float e = 0.f;
    if (t < ACTIONS)       e += expf(v0 - mx);
    if (t + 256 < ACTIONS) e += expf(v1 - mx);
    if (t + 512 < ACTIONS) e += expf(v2 - mx);
    e = warp_sum(e);
    if ((t & 31) == 0) sm[t >> 5] = e;
    __syncthreads();
    if (t < 8) {
        float ss = sm[t];
        #pragma unroll
        for (int o = 4; o > 0; o >>= 1) ss += __shfl_xor_sync(0xffu, ss, o);
        if (t == 0) bshared = ss;
    }
    __syncthreads();
    const float lg = logf(bshared);

    if (t < ACTIONS)       out[t]       = v0 - mx - lg;
    if (t + 256 < ACTIONS) out[t + 256] = v1 - mx - lg;
    if (t + 512 < ACTIONS) out[t + 512] = v2 - mx - lg;
}

// ---------------- launch ----------------
extern "C" void kernel_launch(void* const* d_in, const int* in_sizes, int n_in,
                              void* d_out, int out_size) {
    const float* x    = (const float*)d_in[0];
    const int*   ei   = (const int*)d_in[1];
    const float* Wg   = (const float*)d_in[2];
    const float* bg   = (const float*)d_in[3];
    const float* ln_g = (const float*)d_in[4];
    const float* ln_b = (const float*)d_in[5];
    const float* W1   = (const float*)d_in[6];
    const float* b1   = (const float*)d_in[7];
    const float* W2   = (const float*)d_in[8];
    const float* b2   = (const float*)d_in[9];
    float* out = (float*)d_out;

    kZ<<<(ZTOT + 1023) / 1024, 1024>>>(x, ei);
    kB<<<N_NODES, 512>>>(Wg, bg);
    kD<<<dim3(8, 128), 256>>>(W1, ln_g, ln_b);
    kE<<<dim3(HIDDEN / KC2, 3), 256>>>(W2, b1, b2, out);
}